// round 15
// baseline (speedup 1.0000x reference)
#include <cuda_runtime.h>
#include <stdint.h>

// ---------------------------------------------------------------------------
// W4A8 per-group GEMM, legacy IMMA (tcgen05 rejected by sm_103 PTX target).
//   w_int8[o,k] = q4[o,k]*s2[g,o] + z[g,o]   (exact int8, |w| <= 105)
//   acc[m,o]    = sum_k x_i8[m,k]*w_int8[o,k]  (s32 mma.m16n8k32)
//   out[m,o]    = acc * isc[m] * s1[o] + bias[o]
//
// Round 15 = R8 (best, 68.1us) + three individually-validated reductions:
//  1. A fragments pre-packed s8 in gmem in IMMA register order (R10/R12
//     mechanism) -> no A smem tile, no A ldmatrix, batched per-group LDGs
//  2. cp.async.cg raw qweight (R4/R12) -> no register weight staging
//  3. 2 groups per __syncthreads, 4 B buffers (R11) -> 16 barriers, longer
//     MMA runs
// Consumer phase/group: 4 ldmatrix + 8 IMMA. Producer: dequant smem->smem.
// ---------------------------------------------------------------------------

#define M_DIM 64
#define K_DIM 4096
#define N_DIM 14336
#define G_DIM 32
#define NT    32             // output channels per CTA -> 448 CTAs
#define BROW  144            // padded s8 B-tile row (conflict-free, validated)
#define THREADS 256
#define TILE_B (NT * BROW)           // 4608
#define RAW_BYTES 16384              // one group: 32 rows x 128 ints x 4B
#define OFF_RAW(b)  ((b) * RAW_BYTES)
#define OFF_B(i)    (2 * RAW_BYTES + (i) * TILE_B)
#define SMEM_TOTAL  (2 * RAW_BYTES + 4 * TILE_B)   // 51200

#define CP_ASYNC16(dst, src) \
    asm volatile("cp.async.cg.shared.global [%0], [%1], 16;" :: "r"(dst), "l"(src))
#define CP_COMMIT()  asm volatile("cp.async.commit_group;")
#define CP_WAIT(N)   asm volatile("cp.async.wait_group %0;" :: "n"(N))

__device__ __forceinline__ unsigned smem_u32(const void* p) {
    unsigned a;
    asm("{ .reg .u64 t; cvta.to.shared.u64 t, %1; cvt.u32.u64 %0, t; }" : "=r"(a) : "l"(p));
    return a;
}
__device__ __forceinline__ unsigned pk4(int a, int b, int c, int d) {
    return __byte_perm(__byte_perm((unsigned)a, (unsigned)b, 0x0040),
                       __byte_perm((unsigned)c, (unsigned)d, 0x0040), 0x5410);
}

// A fragments as s8 in IMMA m16n8k32 register order:
// uint4 index = g*512 + wm*128 + ks*32 + lane   (256 KB total)
//   .x=a0(row r0,k kb..kb+3)  .y=a1(r0+8)  .z=a2(r0,kb+16..19)  .w=a3(r0+8)
__device__ __align__(16) uint4 g_x_frag[G_DIM * 4 * 4 * 32];

// ---- pass 0: pack x int32 -> s8 A-fragments -----------------------------------
__global__ void pack_x_frag_kernel(const int* __restrict__ x) {
    const int t = blockIdx.x * blockDim.x + threadIdx.x;
    if (t >= G_DIM * 512) return;
    const int lane = t & 31;
    const int ks   = (t >> 5) & 3;
    const int wm   = (t >> 7) & 3;
    const int g    = t >> 9;
    const int g4 = lane >> 2, tg = lane & 3;
    const int r0 = wm * 16 + g4, r1 = r0 + 8;
    const int kb = g * 128 + ks * 32 + tg * 4;
    const int* p0 = x + r0 * K_DIM + kb;
    const int* p1 = x + r1 * K_DIM + kb;
    uint4 v;
    v.x = pk4(p0[0],  p0[1],  p0[2],  p0[3]);
    v.y = pk4(p1[0],  p1[1],  p1[2],  p1[3]);
    v.z = pk4(p0[16], p0[17], p0[18], p0[19]);
    v.w = pk4(p1[16], p1[17], p1[18], p1[19]);
    g_x_frag[t] = v;
}

// one group's MMA: 4 k32-steps x n16 (this warp's wn slice); A from registers
__device__ __forceinline__ void mma_group(int acc[2][4], const uint4 af[4], unsigned bA) {
#pragma unroll
    for (int ks = 0; ks < 4; ks++) {
        const uint4 a = af[ks];
        unsigned b0, b1, b2, b3;
        asm volatile(
            "ldmatrix.sync.aligned.m8n8.x4.shared.b16 {%0,%1,%2,%3}, [%4];"
            : "=r"(b0), "=r"(b1), "=r"(b2), "=r"(b3)
            : "r"(bA + ks * 32));
        asm volatile(
            "mma.sync.aligned.m16n8k32.row.col.s32.s8.s8.s32 "
            "{%0,%1,%2,%3}, {%4,%5,%6,%7}, {%8,%9}, {%0,%1,%2,%3};\n"
            : "+r"(acc[0][0]), "+r"(acc[0][1]), "+r"(acc[0][2]), "+r"(acc[0][3])
            : "r"(a.x), "r"(a.y), "r"(a.z), "r"(a.w), "r"(b0), "r"(b1));
        asm volatile(
            "mma.sync.aligned.m16n8k32.row.col.s32.s8.s8.s32 "
            "{%0,%1,%2,%3}, {%4,%5,%6,%7}, {%8,%9}, {%0,%1,%2,%3};\n"
            : "+r"(acc[1][0]), "+r"(acc[1][1]), "+r"(acc[1][2]), "+r"(acc[1][3])
            : "r"(a.x), "r"(a.y), "r"(a.z), "r"(a.w), "r"(b2), "r"(b3));
    }
}

// ---- main GEMM ---------------------------------------------------------------
__global__ __launch_bounds__(THREADS, 3)
void w4a8_gemm_kernel(const int*   __restrict__ qw,    // [N,K] int32 (0..15)
                      const int*   __restrict__ s2s,   // [G,N]
                      const int*   __restrict__ s2z,   // [G,N]
                      const float* __restrict__ isc,   // [M]
                      const float* __restrict__ s1,    // [N]
                      const float* __restrict__ bias,  // [N]
                      float*       __restrict__ out)   // [M,N]
{
    extern __shared__ __align__(16) unsigned char smem[];
    const unsigned sbase = smem_u32(smem);

    const int tid = threadIdx.x;
    const int n0  = blockIdx.x * NT;

    // qweight producer mapping (R12-validated): thread -> (row, 64B slice)
    const int brow = tid >> 3;
    const int bseg = tid & 7;
    const char* gsrc = reinterpret_cast<const char*>(qw + (size_t)(n0 + brow) * K_DIM)
                     + bseg * 64;
    const unsigned roffc = (unsigned)brow * 512u + (unsigned)bseg * 16u;
    const unsigned bSto  = (unsigned)brow * BROW + (unsigned)bseg * 16u;

    // MMA mapping: 8 warps = 4(M) x 2(N); warp tile 16m x 16n (R8-validated)
    const int warp = tid >> 5, lane = tid & 31;
    const int wm = warp >> 1;
    const int wn = warp & 1;
    const int g4 = lane >> 2, tg = lane & 3;

    // A-fragment gmem pointer (uint4 units)
    const uint4* aptr = g_x_frag + wm * 128 + lane;

    // B ldmatrix base (buffer 0; R8-validated addressing)
    const unsigned bFrag = sbase + OFF_B(0)
        + (unsigned)(wn * 16 + ((lane >> 4) & 1) * 8 + (lane & 7)) * BROW
        + (unsigned)((lane >> 3) & 1) * 16u;

    int acc[2][4];
#pragma unroll
    for (int i = 0; i < 2; i++)
#pragma unroll
        for (int j = 0; j < 4; j++) acc[i][j] = 0;

    // ---- prologue: stream raw groups 0 (raw0) and 1 (raw1) ----
#pragma unroll
    for (int s = 0; s < 2; s++) {
        const unsigned dst = sbase + OFF_RAW(s) + roffc;
        const char* src = gsrc + (size_t)s * 512;
#pragma unroll
        for (int j = 0; j < 4; j++) CP_ASYNC16(dst + j * 128u, src + j * 16);
        CP_COMMIT();
    }
    int s2a = s2s[n0 + brow],         za = s2z[n0 + brow];
    int s2b = s2s[N_DIM + n0 + brow], zb = s2z[N_DIM + n0 + brow];

    for (int p = 0; p < G_DIM / 2; ++p) {
        const int a  = 2 * p;
        const int bb = 2 * (p & 1);     // B buffer pair {bb, bb+1}

        // A fragments for group a (issued early; L1/L2-hot, 4 LDG.128)
        uint4 af0[4];
        {
            const uint4* ap = aptr + a * 512;
#pragma unroll
            for (int k = 0; k < 4; k++) af0[k] = ap[k * 32];
        }

        // ---- consume raw0/raw1: dequant s8 -> sB[bb]/sB[bb+1], refill ----
        CP_WAIT(1);
#pragma unroll
        for (int h = 0; h < 2; h++) {
            if (h == 1) { if (p == G_DIM / 2 - 1) { CP_WAIT(0); } else { CP_WAIT(1); } }
            const int s2 = h ? s2b : s2a;
            const int zz = h ? zb  : za;
            unsigned pk[4];
#pragma unroll
            for (int j = 0; j < 4; j++) {
                int4 q = *reinterpret_cast<const int4*>(
                    smem + OFF_RAW(h) + roffc + j * 128u);
                pk[j] = pk4(q.x * s2 + zz, q.y * s2 + zz,
                            q.z * s2 + zz, q.w * s2 + zz);
            }
            *reinterpret_cast<uint4*>(smem + OFF_B(bb + h) + bSto) =
                make_uint4(pk[0], pk[1], pk[2], pk[3]);
            // refill this raw buffer with group a+2+h
            if (a + 2 + h < G_DIM) {
                const unsigned rdst = sbase + OFF_RAW(h) + roffc;
                const char* src = gsrc + (size_t)(a + 2 + h) * 512;
#pragma unroll
                for (int j = 0; j < 4; j++) CP_ASYNC16(rdst + j * 128u, src + j * 16);
                CP_COMMIT();
            }
        }

        // ---- prefetch next pair's scales ----
        if (p + 1 < G_DIM / 2) {
            s2a = s2s[(a + 2) * N_DIM + n0 + brow];
            za  = s2z[(a + 2) * N_DIM + n0 + brow];
            s2b = s2s[(a + 3) * N_DIM + n0 + brow];
            zb  = s2z[(a + 3) * N_DIM + n0 + brow];
        }

        __syncthreads();   // ONE barrier per 2 groups

        // ---- issue A frags for group a+1 (hidden under MMA of group a) ----
        uint4 af1[4];
        {
            const uint4* ap = aptr + (a + 1) * 512;
#pragma unroll
            for (int k = 0; k < 4; k++) af1[k] = ap[k * 32];
        }

        // ---- MMA group a, then group a+1 ----
        mma_group(acc, af0, bFrag + (unsigned)bb * TILE_B);
        mma_group(acc, af1, bFrag + (unsigned)(bb + 1) * TILE_B);
    }

    // ---- epilogue: out = acc * isc[m] * s1[n] + bias[n] ----
    const int m0 = wm * 16 + g4;
    const float isc0 = isc[m0];
    const float isc1 = isc[m0 + 8];
#pragma unroll
    for (int ns = 0; ns < 2; ns++) {
        const int n = n0 + wn * 16 + ns * 8 + tg * 2;
        const float s1a = s1[n],   s1b = s1[n + 1];
        const float ba  = bias[n], bb2 = bias[n + 1];
        out[ m0      * N_DIM + n    ] = (float)acc[ns][0] * isc0 * s1a + ba;
        out[ m0      * N_DIM + n + 1] = (float)acc[ns][1] * isc0 * s1b + bb2;
        out[(m0 + 8) * N_DIM + n    ] = (float)acc[ns][2] * isc1 * s1a + ba;
        out[(m0 + 8) * N_DIM + n + 1] = (float)acc[ns][3] * isc1 * s1b + bb2;
    }
}

// ---------------------------------------------------------------------------
extern "C" void kernel_launch(void* const* d_in, const int* in_sizes, int n_in,
                              void* d_out, int out_size) {
    const int*   x    = (const int*)  d_in[0];  // [M,K] int32 (int8 values)
    const float* isc  = (const float*)d_in[1];  // [M]
    // d_in[2] = input_sum (unused)
    const int*   qw   = (const int*)  d_in[3];  // [N,K] int32 (uint4 values)
    const int*   s2s  = (const int*)  d_in[4];  // [G,N]
    const int*   s2z  = (const int*)  d_in[5];  // [G,N]
    const float* s1   = (const float*)d_in[6];  // [N]
    const float* bias = (const float*)d_in[7];  // [N]
    float* out = (float*)d_out;

    cudaFuncSetAttribute(w4a8_gemm_kernel,
                         cudaFuncAttributeMaxDynamicSharedMemorySize, SMEM_TOTAL);

    pack_x_frag_kernel<<<G_DIM * 512 / 256, 256>>>(x);
    w4a8_gemm_kernel<<<N_DIM / NT, THREADS, SMEM_TOTAL>>>(qw, s2s, s2z, isc, s1, bias, out);
}

// round 16
// speedup vs baseline: 1.1317x; 1.1317x over previous
#include <cuda_runtime.h>
#include <stdint.h>

// ---------------------------------------------------------------------------
// W4A8 per-group GEMM, legacy IMMA (tcgen05 rejected by sm_103 PTX target).
//   w_int8[o,k] = q4[o,k]*s2[g,o] + z[g,o]   (exact int8, |w| <= 105)
//   acc[m,o]    = sum_k x_i8[m,k]*w_int8[o,k]  (s32 mma.m16n8k32)
//   out[m,o]    = acc * isc[m] * s1[o] + bias[o]
//
// Round 16 = R8 (best, 68.1us) + exactly ONE change: 2 groups per
// __syncthreads (16 barriers instead of 32). Four A-buffers + four
// B-buffers, BROW=144 addressing byte-identical to R8; register prefetch
// extended to a pair of groups. All other structure = R8 verbatim.
// ---------------------------------------------------------------------------

#define M_DIM 64
#define K_DIM 4096
#define N_DIM 14336
#define G_DIM 32
#define GS    128          // K per group
#define NT    32           // output channels per CTA -> 448 CTAs
#define BROW  144          // padded s8 tile row (conflict-free, validated)
#define THREADS 256
#define TILE_A (M_DIM * BROW)        // 9216
#define TILE_B (NT * BROW)           // 4608
#define OFF_A(i) ((i) * TILE_A)
#define OFF_B(i) (4 * TILE_A + (i) * TILE_B)
#define SMEM_TOTAL (4 * TILE_A + 4 * TILE_B)   // 55296

__device__ __forceinline__ unsigned smem_u32(const void* p) {
    unsigned a;
    asm("{ .reg .u64 t; cvta.to.shared.u64 t, %1; cvt.u32.u64 %0, t; }" : "=r"(a) : "l"(p));
    return a;
}
__device__ __forceinline__ unsigned pk4(int a, int b, int c, int d) {
    return __byte_perm(__byte_perm((unsigned)a, (unsigned)b, 0x0040),
                       __byte_perm((unsigned)c, (unsigned)d, 0x0040), 0x5410);
}

// int8-packed activations [M][K] (256 KB static scratch; validated R1-R8)
__device__ __align__(16) unsigned int g_x_packed[M_DIM * K_DIM / 4];

__global__ void pack_x_kernel(const int* __restrict__ x) {
    int idx = blockIdx.x * blockDim.x + threadIdx.x;
    if (idx >= M_DIM * K_DIM / 4) return;
    const int4 v = reinterpret_cast<const int4*>(x)[idx];
    unsigned a = __byte_perm((unsigned)v.x, (unsigned)v.y, 0x0040);
    unsigned b = __byte_perm((unsigned)v.z, (unsigned)v.w, 0x0040);
    g_x_packed[idx] = __byte_perm(a, b, 0x5410);
}

// one group's MMA from buffers (aOff,bOff): 4 k32-steps x 2 n8-subtiles
__device__ __forceinline__ void mma_group(int acc[2][4], unsigned aOff, unsigned bOff) {
#pragma unroll
    for (int ks = 0; ks < 4; ks++) {
        unsigned a0, a1, a2, a3, b0, b1, b2, b3;
        asm volatile(
            "ldmatrix.sync.aligned.m8n8.x4.shared.b16 {%0,%1,%2,%3}, [%4];"
            : "=r"(a0), "=r"(a1), "=r"(a2), "=r"(a3)
            : "r"(aOff + ks * 32));
        asm volatile(
            "ldmatrix.sync.aligned.m8n8.x4.shared.b16 {%0,%1,%2,%3}, [%4];"
            : "=r"(b0), "=r"(b1), "=r"(b2), "=r"(b3)
            : "r"(bOff + ks * 32));
        asm volatile(
            "mma.sync.aligned.m16n8k32.row.col.s32.s8.s8.s32 "
            "{%0,%1,%2,%3}, {%4,%5,%6,%7}, {%8,%9}, {%0,%1,%2,%3};\n"
            : "+r"(acc[0][0]), "+r"(acc[0][1]), "+r"(acc[0][2]), "+r"(acc[0][3])
            : "r"(a0), "r"(a1), "r"(a2), "r"(a3), "r"(b0), "r"(b1));
        asm volatile(
            "mma.sync.aligned.m16n8k32.row.col.s32.s8.s8.s32 "
            "{%0,%1,%2,%3}, {%4,%5,%6,%7}, {%8,%9}, {%0,%1,%2,%3};\n"
            : "+r"(acc[1][0]), "+r"(acc[1][1]), "+r"(acc[1][2]), "+r"(acc[1][3])
            : "r"(a0), "r"(a1), "r"(a2), "r"(a3), "r"(b2), "r"(b3));
    }
}

// ---- main GEMM ---------------------------------------------------------------
__global__ __launch_bounds__(THREADS, 3)
void w4a8_gemm_kernel(const int*   __restrict__ qw,    // [N,K] int32 (0..15)
                      const int*   __restrict__ s2s,   // [G,N]
                      const int*   __restrict__ s2z,   // [G,N]
                      const float* __restrict__ isc,   // [M]
                      const float* __restrict__ s1,    // [N]
                      const float* __restrict__ bias,  // [N]
                      float*       __restrict__ out)   // [M,N]
{
    extern __shared__ __align__(16) unsigned char smem[];
    const unsigned sbase = smem_u32(smem);

    const int tid = threadIdx.x;
    const int n0  = blockIdx.x * NT;

    // B dequant mapping (R8): thread -> (weight row 0..31, 16-int segment 0..7)
    const int brow = tid >> 3;
    const int bseg = tid & 7;
    const int4* qbase = reinterpret_cast<const int4*>(qw)
                      + (size_t)(n0 + brow) * (K_DIM / 4) + bseg * 4;
    const unsigned bSto = (unsigned)brow * BROW + (unsigned)bseg * 16u;

    // A producer mapping (R8): thread -> two int4 slots (64 rows x 8 chunks)
    const int4* xb = reinterpret_cast<const int4*>(g_x_packed);
    const int u0 = tid, u1 = tid + 256;
    const unsigned aSto0 = (unsigned)(u0 >> 3) * BROW + (unsigned)(u0 & 7) * 16u;
    const unsigned aSto1 = (unsigned)(u1 >> 3) * BROW + (unsigned)(u1 & 7) * 16u;
    const int xIdx0 = (u0 >> 3) * (K_DIM / 16) + (u0 & 7);
    const int xIdx1 = (u1 >> 3) * (K_DIM / 16) + (u1 & 7);

    // MMA mapping (R8): 8 warps as 4(M) x 2(N); warp tile 16m x 16n
    const int warp = tid >> 5, lane = tid & 31;
    const int wm = warp >> 1;
    const int wn = warp & 1;
    const int g4 = lane >> 2, tg = lane & 3;

    const unsigned aFrag = sbase + (unsigned)(wm * 16 + (lane & 15)) * BROW
                               + (unsigned)((lane >> 4) & 1) * 16;
    const unsigned bFrag = sbase + OFF_B(0)
        + (unsigned)(wn * 16 + ((lane >> 4) & 1) * 8 + (lane & 7)) * BROW
        + (unsigned)((lane >> 3) & 1) * 16;

    int acc[2][4];
#pragma unroll
    for (int i = 0; i < 2; i++)
#pragma unroll
        for (int j = 0; j < 4; j++) acc[i][j] = 0;

    // register staging for one PAIR of groups (current + next, R8 style)
    int4 qrA[4], qrB[4], qnA[4], qnB[4];
    int4 xrA[2], xrB[2], xnA[2], xnB[2];
    int  s2A, zA, s2B, zB, s2nA, znA, s2nB, znB;

    // ---- prefetch pair 0 (groups 0,1) ----
#pragma unroll
    for (int j = 0; j < 4; j++) { qrA[j] = qbase[j]; qrB[j] = qbase[(GS / 4) + j]; }
    xrA[0] = xb[xIdx0];                 xrA[1] = xb[xIdx1];
    xrB[0] = xb[xIdx0 + (GS / 16)];     xrB[1] = xb[xIdx1 + (GS / 16)];
    s2A = s2s[n0 + brow];         zA = s2z[n0 + brow];
    s2B = s2s[N_DIM + n0 + brow]; zB = s2z[N_DIM + n0 + brow];

    for (int p = 0; p < G_DIM / 2; ++p) {
        const int g  = 2 * p;
        const int bb = 2 * (p & 1);          // buffer pair {bb, bb+1}

        // ---- dequant + store group g -> bufs[bb], group g+1 -> bufs[bb+1] ----
        {
            unsigned pa[4], pb[4];
#pragma unroll
            for (int j = 0; j < 4; j++) {
                pa[j] = pk4(qrA[j].x * s2A + zA, qrA[j].y * s2A + zA,
                            qrA[j].z * s2A + zA, qrA[j].w * s2A + zA);
                pb[j] = pk4(qrB[j].x * s2B + zB, qrB[j].y * s2B + zB,
                            qrB[j].z * s2B + zB, qrB[j].w * s2B + zB);
            }
            *reinterpret_cast<uint4*>(smem + OFF_B(bb)     + bSto) =
                make_uint4(pa[0], pa[1], pa[2], pa[3]);
            *reinterpret_cast<uint4*>(smem + OFF_B(bb + 1) + bSto) =
                make_uint4(pb[0], pb[1], pb[2], pb[3]);
            *reinterpret_cast<int4*>(smem + OFF_A(bb)     + aSto0) = xrA[0];
            *reinterpret_cast<int4*>(smem + OFF_A(bb)     + aSto1) = xrA[1];
            *reinterpret_cast<int4*>(smem + OFF_A(bb + 1) + aSto0) = xrB[0];
            *reinterpret_cast<int4*>(smem + OFF_A(bb + 1) + aSto1) = xrB[1];
        }

        // ---- prefetch pair p+1 (groups g+2, g+3; clamped) ----
        {
            const int ga = (g + 2 < G_DIM) ? (g + 2) : (G_DIM - 2);
            const int gb = ga + 1;
            const int4* qpa = qbase + ga * (GS / 4);
            const int4* qpb = qbase + gb * (GS / 4);
#pragma unroll
            for (int j = 0; j < 4; j++) { qnA[j] = qpa[j]; qnB[j] = qpb[j]; }
            xnA[0] = xb[xIdx0 + ga * (GS / 16)]; xnA[1] = xb[xIdx1 + ga * (GS / 16)];
            xnB[0] = xb[xIdx0 + gb * (GS / 16)]; xnB[1] = xb[xIdx1 + gb * (GS / 16)];
            s2nA = s2s[ga * N_DIM + n0 + brow];  znA = s2z[ga * N_DIM + n0 + brow];
            s2nB = s2s[gb * N_DIM + n0 + brow];  znB = s2z[gb * N_DIM + n0 + brow];
        }

        __syncthreads();   // ONE barrier per 2 groups

        // ---- MMA group g then g+1 ----
        mma_group(acc, aFrag + (unsigned)(bb)     * TILE_A,
                       bFrag + (unsigned)(bb)     * TILE_B);
        mma_group(acc, aFrag + (unsigned)(bb + 1) * TILE_A,
                       bFrag + (unsigned)(bb + 1) * TILE_B);

        // ---- rotate staging ----
#pragma unroll
        for (int j = 0; j < 4; j++) { qrA[j] = qnA[j]; qrB[j] = qnB[j]; }
        xrA[0] = xnA[0]; xrA[1] = xnA[1];
        xrB[0] = xnB[0]; xrB[1] = xnB[1];
        s2A = s2nA; zA = znA; s2B = s2nB; zB = znB;
    }

    // ---- epilogue (R8): out = acc * isc[m] * s1[n] + bias[n] ----
    const int m0 = wm * 16 + g4;
    const float isc0 = isc[m0];
    const float isc1 = isc[m0 + 8];
#pragma unroll
    for (int ns = 0; ns < 2; ns++) {
        const int n = n0 + wn * 16 + ns * 8 + tg * 2;
        const float s1a = s1[n],   s1b = s1[n + 1];
        const float ba  = bias[n], bb2 = bias[n + 1];
        out[ m0      * N_DIM + n    ] = (float)acc[ns][0] * isc0 * s1a + ba;
        out[ m0      * N_DIM + n + 1] = (float)acc[ns][1] * isc0 * s1b + bb2;
        out[(m0 + 8) * N_DIM + n    ] = (float)acc[ns][2] * isc1 * s1a + ba;
        out[(m0 + 8) * N_DIM + n + 1] = (float)acc[ns][3] * isc1 * s1b + bb2;
    }
}

// ---------------------------------------------------------------------------
extern "C" void kernel_launch(void* const* d_in, const int* in_sizes, int n_in,
                              void* d_out, int out_size) {
    const int*   x    = (const int*)  d_in[0];  // [M,K] int32 (int8 values)
    const float* isc  = (const float*)d_in[1];  // [M]
    // d_in[2] = input_sum (unused)
    const int*   qw   = (const int*)  d_in[3];  // [N,K] int32 (uint4 values)
    const int*   s2s  = (const int*)  d_in[4];  // [G,N]
    const int*   s2z  = (const int*)  d_in[5];  // [G,N]
    const float* s1   = (const float*)d_in[6];  // [N]
    const float* bias = (const float*)d_in[7];  // [N]
    float* out = (float*)d_out;

    cudaFuncSetAttribute(w4a8_gemm_kernel,
                         cudaFuncAttributeMaxDynamicSharedMemorySize, SMEM_TOTAL);

    pack_x_kernel<<<(M_DIM * K_DIM / 4 + 255) / 256, 256>>>(x);
    w4a8_gemm_kernel<<<N_DIM / NT, THREADS, SMEM_TOTAL>>>(qw, s2s, s2z, isc, s1, bias, out);
}

// round 17
// speedup vs baseline: 1.3003x; 1.1490x over previous
#include <cuda_runtime.h>
#include <stdint.h>

// ---------------------------------------------------------------------------
// W4A8 per-group GEMM, legacy IMMA (tcgen05 rejected by sm_103 PTX target).
//   w_int8[o,k] = q4[o,k]*s2[g,o] + z[g,o]   (exact int8, |w| <= 105)
//   acc[m,o]    = sum_k x_i8[m,k]*w_int8[o,k]  (s32 mma.m16n8k32)
//   out[m,o]    = acc * isc[m] * s1[o] + bias[o]
//
// FINAL = Round 8 configuration (best measured: 68.1us, rel_err 4.4e-8).
// 16 subsequent structural experiments (warp specialization, triple-buffer
// interleave, gmem A-fragments, bf16/fp16 HMMA datapaths, barrier halving)
// all landed at 78-105us. This structure is the measured local optimum:
//  - NT=32 -> 448 CTAs (uniform ~3/SM, single wave at launch_bounds(256,4))
//  - register-prefetched raw weights + double-buffered smem A/B tiles
//  - exact-int8 dequant in the load path, one s8 GEMM over full K
//  - ldmatrix.m8n8.x4 fragment loads (BROW=144 conflict-free)
//  - one __syncthreads per K-group
// Remaining wall: legacy mma.sync.s8 pipe throughput (~48us busy).
// ---------------------------------------------------------------------------

#define M_DIM 64
#define K_DIM 4096
#define N_DIM 14336
#define G_DIM 32
#define GS    128          // K per group
#define NT    32           // output channels per CTA -> 448 CTAs
#define BROW  (GS + 16)    // padded smem row (144B): ldmatrix phases conflict-free
#define THREADS 256
#define TILE_A (M_DIM * BROW)   // 9216
#define TILE_B (NT * BROW)      // 4608

__device__ __forceinline__ unsigned smem_u32(const void* p) {
    unsigned a;
    asm("{ .reg .u64 t; cvta.to.shared.u64 t, %1; cvt.u32.u64 %0, t; }" : "=r"(a) : "l"(p));
    return a;
}

// int8-packed activations [M][K] (256 KB static scratch)
__device__ __align__(16) unsigned int g_x_packed[M_DIM * K_DIM / 4];

// ---- pass 0: pack x int32 -> int8 -------------------------------------------
__global__ void pack_x_kernel(const int* __restrict__ x) {
    int idx = blockIdx.x * blockDim.x + threadIdx.x;   // one packed word
    if (idx >= M_DIM * K_DIM / 4) return;
    const int4 v = reinterpret_cast<const int4*>(x)[idx];
    unsigned a = __byte_perm((unsigned)v.x, (unsigned)v.y, 0x0040);
    unsigned b = __byte_perm((unsigned)v.z, (unsigned)v.w, 0x0040);
    g_x_packed[idx] = __byte_perm(a, b, 0x5410);
}

// ---- main GEMM ---------------------------------------------------------------
__global__ __launch_bounds__(THREADS, 4)
void w4a8_gemm_kernel(const int*   __restrict__ qw,    // [N,K] int32 (0..15)
                      const int*   __restrict__ s2s,   // [G,N]
                      const int*   __restrict__ s2z,   // [G,N]
                      const float* __restrict__ isc,   // [M]
                      const float* __restrict__ s1,    // [N]
                      const float* __restrict__ bias,  // [N]
                      float*       __restrict__ out)   // [M,N]
{
    __shared__ __align__(16) unsigned char sA[2][TILE_A]; // x tile 64x128 s8
    __shared__ __align__(16) unsigned char sB[2][TILE_B]; // w tile 32x128 s8

    const int tid = threadIdx.x;
    const int n0  = blockIdx.x * NT;

    // B dequant mapping: thread -> (weight row 0..31, 16-int segment 0..7)
    const int brow = tid >> 3;              // 0..31
    const int bseg = tid & 7;               // 0..7
    const int4* qbase = reinterpret_cast<const int4*>(qw)
                      + (size_t)(n0 + brow) * (K_DIM / 4) + bseg * 4;

    // A producer mapping: thread -> two int4 slots (64 rows x 8 chunks)
    const int4* xb = reinterpret_cast<const int4*>(g_x_packed);

    // MMA mapping: 8 warps as 4(M) x 2(N); warp tile 16m x 16n
    const int warp = tid >> 5, lane = tid & 31;
    const int wm = warp >> 1;               // 0..3
    const int wn = warp & 1;                // 0..1
    const int g4 = lane >> 2, tg = lane & 3;

    // ldmatrix per-lane base addresses (buf 0):
    //  A x4: {M0,M1,M2,M3} = {rows 0-7,rows 8-15} x {bytes 0-15, 16-31}
    //  B x4: {b0(ns0),b1(ns0),b0(ns1),b1(ns1)}
    const unsigned sAu = smem_u32(&sA[0][0]);
    const unsigned sBu = smem_u32(&sB[0][0]);
    const unsigned aFrag = sAu + (unsigned)(wm * 16 + (lane & 15)) * BROW
                               + (unsigned)((lane >> 4) & 1) * 16;
    const unsigned bFrag = sBu + (unsigned)(wn * 16 + ((lane >> 4) & 1) * 8 + (lane & 7)) * BROW
                               + (unsigned)((lane >> 3) & 1) * 16;

    int acc[2][4];
#pragma unroll
    for (int i = 0; i < 2; i++)
#pragma unroll
        for (int j = 0; j < 4; j++) acc[i][j] = 0;

    int4 qr[4], qn[4];   // 16 raw qweight ints (this thread's slice)
    int4 xr[2], xn[2];   // 32 B of packed x (two slots)
    int  s2v, zv, s2n, zn;

    // prefetch group 0
#pragma unroll
    for (int j = 0; j < 4; j++) qr[j] = qbase[j];
#pragma unroll
    for (int j = 0; j < 2; j++) {
        const int u = tid + j * 256;
        xr[j] = xb[(u >> 3) * (K_DIM / 16) + (u & 7)];
    }
    s2v = s2s[n0 + brow];
    zv  = s2z[n0 + brow];

    for (int g = 0; g < G_DIM; ++g) {
        const int buf = g & 1;

        // ---- dequant 16 weights -> s8, store 16B into sB ----
        unsigned pk[4];
#pragma unroll
        for (int j = 0; j < 4; j++) {
            int w0 = qr[j].x * s2v + zv;
            int w1 = qr[j].y * s2v + zv;
            int w2 = qr[j].z * s2v + zv;
            int w3 = qr[j].w * s2v + zv;
            pk[j] = __byte_perm(__byte_perm((unsigned)w0, (unsigned)w1, 0x0040),
                                __byte_perm((unsigned)w2, (unsigned)w3, 0x0040), 0x5410);
        }
        *reinterpret_cast<uint4*>(&sB[buf][brow * BROW + bseg * 16]) =
            make_uint4(pk[0], pk[1], pk[2], pk[3]);
        // ---- store A tile (32B per thread) ----
#pragma unroll
        for (int j = 0; j < 2; j++) {
            const int u = tid + j * 256;
            *reinterpret_cast<int4*>(&sA[buf][(u >> 3) * BROW + (u & 7) * 16]) = xr[j];
        }

        // ---- prefetch next group into registers (covered by MMA phase) ----
        if (g + 1 < G_DIM) {
            const int4* qp = qbase + (g + 1) * (GS / 4);
#pragma unroll
            for (int j = 0; j < 4; j++) qn[j] = qp[j];
#pragma unroll
            for (int j = 0; j < 2; j++) {
                const int u = tid + j * 256;
                xn[j] = xb[(u >> 3) * (K_DIM / 16) + (g + 1) * (GS / 16) + (u & 7)];
            }
            s2n = s2s[(g + 1) * N_DIM + n0 + brow];
            zn  = s2z[(g + 1) * N_DIM + n0 + brow];
        }

        __syncthreads();   // tile (buf) complete; double buffer => 1 sync/iter

        // ---- MMA over this K=128 chunk: 4 k32-steps x 2 n8-subtiles ----
        const unsigned aOff = aFrag + (unsigned)buf * TILE_A;
        const unsigned bOff = bFrag + (unsigned)buf * TILE_B;
#pragma unroll
        for (int ks = 0; ks < 4; ks++) {
            unsigned a0, a1, a2, a3, b0, b1, b2, b3;
            asm volatile(
                "ldmatrix.sync.aligned.m8n8.x4.shared.b16 {%0,%1,%2,%3}, [%4];"
                : "=r"(a0), "=r"(a1), "=r"(a2), "=r"(a3)
                : "r"(aOff + ks * 32));
            asm volatile(
                "ldmatrix.sync.aligned.m8n8.x4.shared.b16 {%0,%1,%2,%3}, [%4];"
                : "=r"(b0), "=r"(b1), "=r"(b2), "=r"(b3)
                : "r"(bOff + ks * 32));
            asm volatile(
                "mma.sync.aligned.m16n8k32.row.col.s32.s8.s8.s32 "
                "{%0,%1,%2,%3}, {%4,%5,%6,%7}, {%8,%9}, {%0,%1,%2,%3};\n"
                : "+r"(acc[0][0]), "+r"(acc[0][1]), "+r"(acc[0][2]), "+r"(acc[0][3])
                : "r"(a0), "r"(a1), "r"(a2), "r"(a3), "r"(b0), "r"(b1));
            asm volatile(
                "mma.sync.aligned.m16n8k32.row.col.s32.s8.s8.s32 "
                "{%0,%1,%2,%3}, {%4,%5,%6,%7}, {%8,%9}, {%0,%1,%2,%3};\n"
                : "+r"(acc[1][0]), "+r"(acc[1][1]), "+r"(acc[1][2]), "+r"(acc[1][3])
                : "r"(a0), "r"(a1), "r"(a2), "r"(a3), "r"(b2), "r"(b3));
        }

        // rotate prefetch registers
#pragma unroll
        for (int j = 0; j < 4; j++) qr[j] = qn[j];
#pragma unroll
        for (int j = 0; j < 2; j++) xr[j] = xn[j];
        s2v = s2n; zv = zn;
    }

    // ---- epilogue: out = acc * isc[m] * s1[n] + bias[n] ----
    const int m0 = wm * 16 + g4;
    const float isc0 = isc[m0];
    const float isc1 = isc[m0 + 8];
#pragma unroll
    for (int ns = 0; ns < 2; ns++) {
        const int n = n0 + wn * 16 + ns * 8 + tg * 2;
        const float s1a = s1[n],   s1b = s1[n + 1];
        const float ba  = bias[n], bb  = bias[n + 1];
        out[ m0      * N_DIM + n    ] = (float)acc[ns][0] * isc0 * s1a + ba;
        out[ m0      * N_DIM + n + 1] = (float)acc[ns][1] * isc0 * s1b + bb;
        out[(m0 + 8) * N_DIM + n    ] = (float)acc[ns][2] * isc1 * s1a + ba;
        out[(m0 + 8) * N_DIM + n + 1] = (float)acc[ns][3] * isc1 * s1b + bb;
    }
}

// ---------------------------------------------------------------------------
extern "C" void kernel_launch(void* const* d_in, const int* in_sizes, int n_in,
                              void* d_out, int out_size) {
    const int*   x    = (const int*)  d_in[0];  // [M,K] int32 (int8 values)
    const float* isc  = (const float*)d_in[1];  // [M]
    // d_in[2] = input_sum (unused)
    const int*   qw   = (const int*)  d_in[3];  // [N,K] int32 (uint4 values)
    const int*   s2s  = (const int*)  d_in[4];  // [G,N]
    const int*   s2z  = (const int*)  d_in[5];  // [G,N]
    const float* s1   = (const float*)d_in[6];  // [N]
    const float* bias = (const float*)d_in[7];  // [N]
    float* out = (float*)d_out;

    pack_x_kernel<<<(M_DIM * K_DIM / 4 + 255) / 256, 256>>>(x);
    w4a8_gemm_kernel<<<N_DIM / NT, THREADS>>>(qw, s2s, s2z, isc, s1, bias, out);
}